// round 2
// baseline (speedup 1.0000x reference)
#include <cuda_runtime.h>
#include <math.h>
#include <stdint.h>

#define BATCH   32
#define DMODEL  4096
#define NH      32
#define NKV     8
#define GSZ     4          // NH / NKV
#define HD      128
#define QKV_COLS 6144      // (NH + 2*NKV) * HD
#define PBLOCK  64
#define NBLK    64
#define SPLITS  8
#define SPLIT_LEN 512      // 4096 / SPLITS
#define KSPLIT  16
#define KCHUNK  256        // 4096 / KSPLIT

// ------------------------------ scratch -------------------------------------
__device__ float g_qkv_part[KSPLIT][BATCH][QKV_COLS];   // 12.6 MB
__device__ float g_q[BATCH][NH][HD];                    // prescaled by 1/sqrt(HD)
__device__ float g_knew[BATCH][NKV][HD];
__device__ float g_vnew[BATCH][NKV][HD];
__device__ float g_po[BATCH][NKV][GSZ][SPLITS][HD];     // 4 MB
__device__ float g_pm[BATCH][NKV][GSZ][SPLITS];
__device__ float g_pl[BATCH][NKV][GSZ][SPLITS];
__device__ float g_attn[BATCH][NH * HD];
__device__ float g_out_part[KSPLIT][BATCH][DMODEL];     // 8.4 MB

// --------------------- K-split 32-row GEMM:  part[s] = x_chunk @ w_chunk ----
// x: [32, 4096] row-major.  w: [4096, ncols] row-major.
// grid: (ncols/128, KSPLIT), block: 128.  One thread = one column, 32 rows.
__global__ __launch_bounds__(128) void gemm32(const float* __restrict__ x,
                                              const float* __restrict__ w,
                                              float* __restrict__ part,
                                              int ncols) {
    __shared__ float hs[BATCH][KCHUNK];                 // 32 KB
    const int col = blockIdx.x * 128 + threadIdx.x;
    const int k0  = blockIdx.y * KCHUNK;

    // stage x chunk: 32 x 256 floats, coalesced float4
    for (int i = threadIdx.x; i < BATCH * (KCHUNK / 4); i += 128) {
        int b  = i >> 6;           // / (KCHUNK/4)
        int kk = i & 63;
        ((float4*)hs[b])[kk] = ((const float4*)(x + (size_t)b * DMODEL + k0))[kk];
    }
    __syncthreads();

    float acc[BATCH];
#pragma unroll
    for (int b = 0; b < BATCH; b++) acc[b] = 0.f;

    const float* wp = w + (size_t)k0 * ncols + col;
#pragma unroll 4
    for (int k = 0; k < KCHUNK; k += 4) {
        float w0 = wp[(size_t)(k + 0) * ncols];
        float w1 = wp[(size_t)(k + 1) * ncols];
        float w2 = wp[(size_t)(k + 2) * ncols];
        float w3 = wp[(size_t)(k + 3) * ncols];
#pragma unroll
        for (int b = 0; b < BATCH; b++) {
            float4 h4 = *(const float4*)&hs[b][k];
            acc[b] = fmaf(h4.x, w0, acc[b]);
            acc[b] = fmaf(h4.y, w1, acc[b]);
            acc[b] = fmaf(h4.z, w2, acc[b]);
            acc[b] = fmaf(h4.w, w3, acc[b]);
        }
    }
    float* op = part + ((size_t)blockIdx.y * BATCH) * ncols + col;
#pragma unroll
    for (int b = 0; b < BATCH; b++) op[(size_t)b * ncols] = acc[b];
}

// ----------------- reduce k-splits of QKV + RoPE + split q/k/v --------------
// 32 * 48 heads * 64 pairs = 98304 threads
__global__ __launch_bounds__(256) void rope_reduce(const int* __restrict__ pos_ids) {
    int idx = blockIdx.x * 256 + threadIdx.x;
    int j  = idx & 63;
    int hh = (idx >> 6) % 48;
    int b  = idx / (48 * 64);

    int c1 = hh * HD + j;
    int c2 = c1 + 64;
    float x1 = 0.f, x2 = 0.f;
#pragma unroll
    for (int s = 0; s < KSPLIT; s++) {
        x1 += g_qkv_part[s][b][c1];
        x2 += g_qkv_part[s][b][c2];
    }
    if (hh < 40) {  // q or k head: rotate-half rope
        float invf = exp2f(-(float)j * (19.931568569324174f / 64.f)); // 1e6^(-j/64)
        float ang  = (float)pos_ids[b] * invf;
        float c = cosf(ang), s = sinf(ang);
        float y1 = x1 * c - x2 * s;
        float y2 = x2 * c + x1 * s;
        if (hh < 32) {
            const float sc = 0.08838834764831845f;   // 1/sqrt(128)
            g_q[b][hh][j]      = y1 * sc;
            g_q[b][hh][j + 64] = y2 * sc;
        } else {
            g_knew[b][hh - 32][j]      = y1;
            g_knew[b][hh - 32][j + 64] = y2;
        }
    } else {
        g_vnew[b][hh - 40][j]      = x1;
        g_vnew[b][hh - 40][j + 64] = x2;
    }
}

// ------------------------- split-KV flash-decode ----------------------------
// grid: (SPLITS, NKV, BATCH), block 256 (8 warps). Each CTA: 512 positions.
__global__ __launch_bounds__(256) void attn_split(const float* __restrict__ kc,
                                                  const float* __restrict__ vc,
                                                  const int* __restrict__ btab,
                                                  const int* __restrict__ seqlens) {
    const int s   = blockIdx.x;
    const int kvh = blockIdx.y;
    const int b   = blockIdx.z;

    __shared__ float4 qs4[GSZ][HD / 4];       // 2 KB
    __shared__ float  ps[GSZ][SPLIT_LEN];     // 8 KB  (scores, then p)
    __shared__ int    phys[8];
    __shared__ float  wmax[8][GSZ];
    __shared__ float  gm[GSZ];
    __shared__ float  wsum[8];
    __shared__ float  red[8][GSZ][HD];        // 16 KB

    const int t    = threadIdx.x;
    const int w    = t >> 5;
    const int lane = t & 31;
    const int kvlen  = seqlens[b];
    const int newpos = kvlen - 1;

    // load q (prescaled)
    for (int i = t; i < GSZ * (HD / 4); i += 256) {
        int g = i >> 5, dd = i & 31;
        qs4[g][dd] = ((const float4*)&g_q[b][kvh * GSZ + g][0])[dd];
    }
    if (t < 8) phys[t] = btab[b * NBLK + s * 8 + t];
    __syncthreads();

    // ---------------- phase A: scores ----------------
    const int lsub = lane >> 3;      // which of 4 positions in the warp-iter
    const int dch  = lane & 7;       // 16-dim chunk
    float4 qr[GSZ][4];
#pragma unroll
    for (int g = 0; g < GSZ; g++)
#pragma unroll
        for (int q = 0; q < 4; q++) qr[g][q] = qs4[g][dch * 4 + q];

    float mloc[GSZ];
#pragma unroll
    for (int g = 0; g < GSZ; g++) mloc[g] = -1e30f;

    const float* kblock = kc + ((size_t)phys[w] * PBLOCK) * NKV * HD + (size_t)kvh * HD;
#pragma unroll 2
    for (int i = 0; i < 16; i++) {
        const int slot = i * 4 + lsub;
        const int l  = w * 64 + slot;
        const int gl = s * SPLIT_LEN + l;
        const float* kp = kblock + (size_t)slot * NKV * HD;
        if (gl == newpos) kp = &g_knew[b][kvh][0];
        float4 kv[4];
#pragma unroll
        for (int q = 0; q < 4; q++) kv[q] = ((const float4*)kp)[dch * 4 + q];

        float sacc[GSZ];
#pragma unroll
        for (int g = 0; g < GSZ; g++) {
            float acc = 0.f;
#pragma unroll
            for (int q = 0; q < 4; q++) {
                acc = fmaf(qr[g][q].x, kv[q].x, acc);
                acc = fmaf(qr[g][q].y, kv[q].y, acc);
                acc = fmaf(qr[g][q].z, kv[q].z, acc);
                acc = fmaf(qr[g][q].w, kv[q].w, acc);
            }
            sacc[g] = acc;
        }
#pragma unroll
        for (int off = 1; off < 8; off <<= 1)
#pragma unroll
            for (int g = 0; g < GSZ; g++)
                sacc[g] += __shfl_xor_sync(0xffffffff, sacc[g], off);
        if (dch == 0) {
#pragma unroll
            for (int g = 0; g < GSZ; g++) {
                float sv = (gl < kvlen) ? sacc[g] : -1e30f;
                ps[g][l] = sv;
                mloc[g] = fmaxf(mloc[g], sv);
            }
        }
    }
#pragma unroll
    for (int off = 16; off >= 1; off >>= 1)
#pragma unroll
        for (int g = 0; g < GSZ; g++)
            mloc[g] = fmaxf(mloc[g], __shfl_xor_sync(0xffffffff, mloc[g], off));
    if (lane == 0)
#pragma unroll
        for (int g = 0; g < GSZ; g++) wmax[w][g] = mloc[g];
    __syncthreads();
    if (t < GSZ) {
        float m = wmax[0][t];
#pragma unroll
        for (int ww = 1; ww < 8; ww++) m = fmaxf(m, wmax[ww][t]);
        gm[t] = m;
    }
    __syncthreads();

    // ---------------- phase B: exp + row sum ----------------
    {
        const int g = t >> 6, lb = t & 63;
        const float m = gm[g];
        float psum = 0.f;
#pragma unroll
        for (int i = 0; i < 8; i++) {
            int l = lb + 64 * i;
            float sv = ps[g][l];
            float p = (sv > -1e29f) ? __expf(sv - m) : 0.f;
            ps[g][l] = p;
            psum += p;
        }
#pragma unroll
        for (int off = 16; off >= 1; off >>= 1)
            psum += __shfl_xor_sync(0xffffffff, psum, off);
        if (lane == 0) wsum[w] = psum;
    }
    __syncthreads();
    if (t < GSZ) {
        g_pm[b][kvh][t][s] = gm[t];
        g_pl[b][kvh][t][s] = wsum[2 * t] + wsum[2 * t + 1];
    }

    // ---------------- phase C: p @ V ----------------
    float4 acc[GSZ];
#pragma unroll
    for (int g = 0; g < GSZ; g++) acc[g] = make_float4(0.f, 0.f, 0.f, 0.f);

#pragma unroll 2
    for (int i = 0; i < 64; i++) {
        const int l = i * 8 + w;                 // whole warp: same l
        const int gl = s * SPLIT_LEN + l;
        if (gl < kvlen) {
            const int blk = l >> 6, slot = l & 63;
            const float* vp = vc + ((size_t)phys[blk] * PBLOCK + slot) * NKV * HD
                                 + (size_t)kvh * HD;
            if (gl == newpos) vp = &g_vnew[b][kvh][0];
            float4 v4 = ((const float4*)vp)[lane];
#pragma unroll
            for (int g = 0; g < GSZ; g++) {
                float p = ps[g][l];
                acc[g].x = fmaf(p, v4.x, acc[g].x);
                acc[g].y = fmaf(p, v4.y, acc[g].y);
                acc[g].z = fmaf(p, v4.z, acc[g].z);
                acc[g].w = fmaf(p, v4.w, acc[g].w);
            }
        }
    }
#pragma unroll
    for (int g = 0; g < GSZ; g++)
        ((float4*)&red[w][g][0])[lane] = acc[g];
    __syncthreads();

    for (int idx = t; idx < GSZ * HD; idx += 256) {
        int g = idx >> 7, d = idx & 127;
        float sum = 0.f;
#pragma unroll
        for (int ww = 0; ww < 8; ww++) sum += red[ww][g][d];
        g_po[b][kvh][g][s][d] = sum;
    }
}

// ----------------------- combine split partials -----------------------------
// grid: BATCH*NH = 1024 blocks, 128 threads (one per d)
__global__ __launch_bounds__(128) void combine_splits() {
    const int bh = blockIdx.x;
    const int b = bh >> 5, h = bh & 31;
    const int kvh = h >> 2, g = h & 3;
    const int d = threadIdx.x;

    float m = -1e30f;
#pragma unroll
    for (int s = 0; s < SPLITS; s++) m = fmaxf(m, g_pm[b][kvh][g][s]);
    float denom = 0.f, e[SPLITS];
#pragma unroll
    for (int s = 0; s < SPLITS; s++) {
        e[s] = __expf(g_pm[b][kvh][g][s] - m);
        denom += e[s] * g_pl[b][kvh][g][s];
    }
    float o = 0.f;
#pragma unroll
    for (int s = 0; s < SPLITS; s++) o += e[s] * g_po[b][kvh][g][s][d];
    g_attn[b][h * HD + d] = o / denom;
}

// ----------------------- final k-split reduce -------------------------------
__global__ __launch_bounds__(256) void final_reduce(float* __restrict__ out) {
    int e = blockIdx.x * 256 + threadIdx.x;        // over 32*4096
    const float* p = &g_out_part[0][0][0];
    float sum = 0.f;
#pragma unroll
    for (int s = 0; s < KSPLIT; s++) sum += p[(size_t)s * BATCH * DMODEL + e];
    out[e] = sum;
}

// ---------------------------------------------------------------------------
extern "C" void kernel_launch(void* const* d_in, const int* in_sizes, int n_in,
                              void* d_out, int out_size) {
    const float* hid  = (const float*)d_in[0];
    const float* wqkv = (const float*)d_in[1];
    const float* wo   = (const float*)d_in[2];
    const float* kc   = (const float*)d_in[3];
    const float* vc   = (const float*)d_in[4];
    const int*   pos  = (const int*)d_in[5];
    const int*   btab = (const int*)d_in[6];
    const int*   slen = (const int*)d_in[7];
    float* out = (float*)d_out;

    void *p_qkv_part, *p_attn, *p_out_part;
    cudaGetSymbolAddress(&p_qkv_part, g_qkv_part);
    cudaGetSymbolAddress(&p_attn, g_attn);
    cudaGetSymbolAddress(&p_out_part, g_out_part);

    gemm32<<<dim3(QKV_COLS / 128, KSPLIT), 128>>>(hid, wqkv, (float*)p_qkv_part, QKV_COLS);
    rope_reduce<<<(BATCH * 48 * 64) / 256, 256>>>(pos);
    attn_split<<<dim3(SPLITS, NKV, BATCH), 256>>>(kc, vc, btab, slen);
    combine_splits<<<BATCH * NH, 128>>>();
    gemm32<<<dim3(DMODEL / 128, KSPLIT), 128>>>((const float*)p_attn, wo, (float*)p_out_part, DMODEL);
    final_reduce<<<(BATCH * DMODEL) / 256, 256>>>(out);
}

// round 3
// speedup vs baseline: 1.0357x; 1.0357x over previous
#include <cuda_runtime.h>
#include <math.h>
#include <stdint.h>

#define BATCH   32
#define DMODEL  4096
#define NH      32
#define NKV     8
#define GSZ     4          // NH / NKV
#define HD      128
#define QKV_COLS 6144      // (NH + 2*NKV) * HD
#define PBLOCK  64
#define NBLK    64
#define SPLITS  8
#define SPLIT_LEN 512      // 4096 / SPLITS
#define KSPLIT  16
#define KCHUNK  256        // 4096 / KSPLIT

typedef unsigned long long u64;

// -------------------- packed f32x2 helpers (sm_100+) ------------------------
__device__ __forceinline__ u64 ffma2(u64 a, u64 b, u64 c) {
    u64 d;
    asm("fma.rn.f32x2 %0, %1, %2, %3;" : "=l"(d) : "l"(a), "l"(b), "l"(c));
    return d;
}
__device__ __forceinline__ u64 pack2(float lo, float hi) {
    u64 r;
    asm("mov.b64 %0, {%1, %2};" : "=l"(r) : "f"(lo), "f"(hi));
    return r;
}
__device__ __forceinline__ float2 unpack2(u64 v) {
    float2 f;
    asm("mov.b64 {%0, %1}, %2;" : "=f"(f.x), "=f"(f.y) : "l"(v));
    return f;
}
union F4 {
    float4 f4;
    struct { u64 lo, hi; } u;
};

// ------------------------------ scratch -------------------------------------
__device__ float g_qkv_part[KSPLIT][BATCH][QKV_COLS];   // 12.6 MB
__device__ float g_q[BATCH][NH][HD];                    // prescaled by 1/sqrt(HD)
__device__ float g_knew[BATCH][NKV][HD];
__device__ float g_vnew[BATCH][NKV][HD];
__device__ float g_po[BATCH][NKV][GSZ][SPLITS][HD];     // 4 MB
__device__ float g_pm[BATCH][NKV][GSZ][SPLITS];
__device__ float g_pl[BATCH][NKV][GSZ][SPLITS];
__device__ float g_attn[BATCH][NH * HD];
__device__ float g_out_part[KSPLIT][BATCH][DMODEL];     // 8.4 MB

// --------------------- K-split 32-row GEMM:  part[s] = x_chunk @ w_chunk ----
// x: [32, 4096] row-major.  w: [4096, ncols] row-major.
// grid: (ncols/128, KSPLIT), block: 128.  One thread = one column, 32 rows.
// Inner math uses packed fma.rn.f32x2: 16 FFMA2 per k-step instead of 32 FFMA.
__global__ __launch_bounds__(128) void gemm32(const float* __restrict__ x,
                                              const float* __restrict__ w,
                                              float* __restrict__ part,
                                              int ncols) {
    __shared__ float hs[BATCH][KCHUNK];                 // 32 KB
    const int col = blockIdx.x * 128 + threadIdx.x;
    const int k0  = blockIdx.y * KCHUNK;

    // stage x chunk: 32 x 256 floats, coalesced float4
    for (int i = threadIdx.x; i < BATCH * (KCHUNK / 4); i += 128) {
        int b  = i >> 6;           // / (KCHUNK/4)
        int kk = i & 63;
        ((float4*)hs[b])[kk] = ((const float4*)(x + (size_t)b * DMODEL + k0))[kk];
    }
    __syncthreads();

    u64 acc2[BATCH];
#pragma unroll
    for (int b = 0; b < BATCH; b++) acc2[b] = 0ULL;   // {0.f, 0.f}

    const float* wp = w + (size_t)k0 * ncols + col;
#pragma unroll 2
    for (int k = 0; k < KCHUNK; k += 4) {
        float w0 = wp[(size_t)(k + 0) * ncols];
        float w1 = wp[(size_t)(k + 1) * ncols];
        float w2 = wp[(size_t)(k + 2) * ncols];
        float w3 = wp[(size_t)(k + 3) * ncols];
        u64 w01 = pack2(w0, w1);
        u64 w23 = pack2(w2, w3);
#pragma unroll
        for (int b = 0; b < BATCH; b++) {
            F4 h;
            h.f4 = *(const float4*)&hs[b][k];
            acc2[b] = ffma2(h.u.lo, w01, ffma2(h.u.hi, w23, acc2[b]));
        }
    }
    float* op = part + ((size_t)blockIdx.y * BATCH) * ncols + col;
#pragma unroll
    for (int b = 0; b < BATCH; b++) {
        float2 f = unpack2(acc2[b]);
        op[(size_t)b * ncols] = f.x + f.y;
    }
}

// ----------------- reduce k-splits of QKV + RoPE + split q/k/v --------------
// 32 * 48 heads * 64 pairs = 98304 threads
__global__ __launch_bounds__(256) void rope_reduce(const int* __restrict__ pos_ids) {
    int idx = blockIdx.x * 256 + threadIdx.x;
    int j  = idx & 63;
    int hh = (idx >> 6) % 48;
    int b  = idx / (48 * 64);

    int c1 = hh * HD + j;
    int c2 = c1 + 64;
    float x1 = 0.f, x2 = 0.f;
#pragma unroll
    for (int s = 0; s < KSPLIT; s++) {
        x1 += g_qkv_part[s][b][c1];
        x2 += g_qkv_part[s][b][c2];
    }
    if (hh < 40) {  // q or k head: rotate-half rope
        float invf = exp2f(-(float)j * (19.931568569324174f / 64.f)); // 1e6^(-j/64)
        float ang  = (float)pos_ids[b] * invf;
        float c = cosf(ang), s = sinf(ang);
        float y1 = x1 * c - x2 * s;
        float y2 = x2 * c + x1 * s;
        if (hh < 32) {
            const float sc = 0.08838834764831845f;   // 1/sqrt(128)
            g_q[b][hh][j]      = y1 * sc;
            g_q[b][hh][j + 64] = y2 * sc;
        } else {
            g_knew[b][hh - 32][j]      = y1;
            g_knew[b][hh - 32][j + 64] = y2;
        }
    } else {
        g_vnew[b][hh - 40][j]      = x1;
        g_vnew[b][hh - 40][j + 64] = x2;
    }
}

// ------------------------- split-KV flash-decode ----------------------------
// grid: (SPLITS, NKV, BATCH), block 256 (8 warps). Each CTA: 512 positions.
__global__ __launch_bounds__(256) void attn_split(const float* __restrict__ kc,
                                                  const float* __restrict__ vc,
                                                  const int* __restrict__ btab,
                                                  const int* __restrict__ seqlens) {
    const int s   = blockIdx.x;
    const int kvh = blockIdx.y;
    const int b   = blockIdx.z;

    __shared__ float4 qs4[GSZ][HD / 4];       // 2 KB
    __shared__ float  ps[GSZ][SPLIT_LEN];     // 8 KB  (scores, then p)
    __shared__ int    phys[8];
    __shared__ float  wmax[8][GSZ];
    __shared__ float  gm[GSZ];
    __shared__ float  wsum[8];
    __shared__ float  red[8][GSZ][HD];        // 16 KB

    const int t    = threadIdx.x;
    const int w    = t >> 5;
    const int lane = t & 31;
    const int kvlen  = seqlens[b];
    const int newpos = kvlen - 1;

    // load q (prescaled)
    for (int i = t; i < GSZ * (HD / 4); i += 256) {
        int g = i >> 5, dd = i & 31;
        qs4[g][dd] = ((const float4*)&g_q[b][kvh * GSZ + g][0])[dd];
    }
    if (t < 8) phys[t] = btab[b * NBLK + s * 8 + t];
    __syncthreads();

    // ---------------- phase A: scores ----------------
    const int lsub = lane >> 3;      // which of 4 positions in the warp-iter
    const int dch  = lane & 7;       // 16-dim chunk
    F4 qr[GSZ][4];
#pragma unroll
    for (int g = 0; g < GSZ; g++)
#pragma unroll
        for (int q = 0; q < 4; q++) qr[g][q].f4 = qs4[g][dch * 4 + q];

    float mloc[GSZ];
#pragma unroll
    for (int g = 0; g < GSZ; g++) mloc[g] = -1e30f;

    const float* kblock = kc + ((size_t)phys[w] * PBLOCK) * NKV * HD + (size_t)kvh * HD;
#pragma unroll 2
    for (int i = 0; i < 16; i++) {
        const int slot = i * 4 + lsub;
        const int l  = w * 64 + slot;
        const int gl = s * SPLIT_LEN + l;
        const float* kp = kblock + (size_t)slot * NKV * HD;
        if (gl == newpos) kp = &g_knew[b][kvh][0];
        F4 kv[4];
#pragma unroll
        for (int q = 0; q < 4; q++) kv[q].f4 = ((const float4*)kp)[dch * 4 + q];

        float sacc[GSZ];
#pragma unroll
        for (int g = 0; g < GSZ; g++) {
            u64 a2 = 0ULL;
#pragma unroll
            for (int q = 0; q < 4; q++) {
                a2 = ffma2(qr[g][q].u.lo, kv[q].u.lo, a2);
                a2 = ffma2(qr[g][q].u.hi, kv[q].u.hi, a2);
            }
            float2 f = unpack2(a2);
            sacc[g] = f.x + f.y;
        }
#pragma unroll
        for (int off = 1; off < 8; off <<= 1)
#pragma unroll
            for (int g = 0; g < GSZ; g++)
                sacc[g] += __shfl_xor_sync(0xffffffff, sacc[g], off);
        if (dch == 0) {
#pragma unroll
            for (int g = 0; g < GSZ; g++) {
                float sv = (gl < kvlen) ? sacc[g] : -1e30f;
                ps[g][l] = sv;
                mloc[g] = fmaxf(mloc[g], sv);
            }
        }
    }
#pragma unroll
    for (int off = 16; off >= 1; off >>= 1)
#pragma unroll
        for (int g = 0; g < GSZ; g++)
            mloc[g] = fmaxf(mloc[g], __shfl_xor_sync(0xffffffff, mloc[g], off));
    if (lane == 0)
#pragma unroll
        for (int g = 0; g < GSZ; g++) wmax[w][g] = mloc[g];
    __syncthreads();
    if (t < GSZ) {
        float m = wmax[0][t];
#pragma unroll
        for (int ww = 1; ww < 8; ww++) m = fmaxf(m, wmax[ww][t]);
        gm[t] = m;
    }
    __syncthreads();

    // ---------------- phase B: exp + row sum ----------------
    {
        const int g = t >> 6, lb = t & 63;
        const float m = gm[g];
        float psum = 0.f;
#pragma unroll
        for (int i = 0; i < 8; i++) {
            int l = lb + 64 * i;
            float sv = ps[g][l];
            float p = (sv > -1e29f) ? __expf(sv - m) : 0.f;
            ps[g][l] = p;
            psum += p;
        }
#pragma unroll
        for (int off = 16; off >= 1; off >>= 1)
            psum += __shfl_xor_sync(0xffffffff, psum, off);
        if (lane == 0) wsum[w] = psum;
    }
    __syncthreads();
    if (t < GSZ) {
        g_pm[b][kvh][t][s] = gm[t];
        g_pl[b][kvh][t][s] = wsum[2 * t] + wsum[2 * t + 1];
    }

    // ---------------- phase C: p @ V ----------------
    u64 acc2[GSZ][2];
#pragma unroll
    for (int g = 0; g < GSZ; g++) { acc2[g][0] = 0ULL; acc2[g][1] = 0ULL; }

#pragma unroll 4
    for (int i = 0; i < 64; i++) {
        const int l = i * 8 + w;                 // whole warp: same l
        const int gl = s * SPLIT_LEN + l;
        if (gl < kvlen) {
            const int blk = l >> 6, slot = l & 63;
            const float* vp = vc + ((size_t)phys[blk] * PBLOCK + slot) * NKV * HD
                                 + (size_t)kvh * HD;
            if (gl == newpos) vp = &g_vnew[b][kvh][0];
            F4 v4;
            v4.f4 = ((const float4*)vp)[lane];
#pragma unroll
            for (int g = 0; g < GSZ; g++) {
                u64 p2 = pack2(ps[g][l], ps[g][l]);
                acc2[g][0] = ffma2(p2, v4.u.lo, acc2[g][0]);
                acc2[g][1] = ffma2(p2, v4.u.hi, acc2[g][1]);
            }
        }
    }
#pragma unroll
    for (int g = 0; g < GSZ; g++) {
        F4 o;
        o.u.lo = acc2[g][0];
        o.u.hi = acc2[g][1];
        ((float4*)&red[w][g][0])[lane] = o.f4;
    }
    __syncthreads();

    for (int idx = t; idx < GSZ * HD; idx += 256) {
        int g = idx >> 7, d = idx & 127;
        float sum = 0.f;
#pragma unroll
        for (int ww = 0; ww < 8; ww++) sum += red[ww][g][d];
        g_po[b][kvh][g][s][d] = sum;
    }
}

// ----------------------- combine split partials -----------------------------
// grid: BATCH*NH = 1024 blocks, 128 threads (one per d)
__global__ __launch_bounds__(128) void combine_splits() {
    const int bh = blockIdx.x;
    const int b = bh >> 5, h = bh & 31;
    const int kvh = h >> 2, g = h & 3;
    const int d = threadIdx.x;

    float m = -1e30f;
#pragma unroll
    for (int s = 0; s < SPLITS; s++) m = fmaxf(m, g_pm[b][kvh][g][s]);
    float denom = 0.f, e[SPLITS];
#pragma unroll
    for (int s = 0; s < SPLITS; s++) {
        e[s] = __expf(g_pm[b][kvh][g][s] - m);
        denom += e[s] * g_pl[b][kvh][g][s];
    }
    float o = 0.f;
#pragma unroll
    for (int s = 0; s < SPLITS; s++) o += e[s] * g_po[b][kvh][g][s][d];
    g_attn[b][h * HD + d] = o / denom;
}

// ----------------------- final k-split reduce -------------------------------
__global__ __launch_bounds__(256) void final_reduce(float* __restrict__ out) {
    int e = blockIdx.x * 256 + threadIdx.x;        // over 32*4096
    const float* p = &g_out_part[0][0][0];
    float sum = 0.f;
#pragma unroll
    for (int s = 0; s < KSPLIT; s++) sum += p[(size_t)s * BATCH * DMODEL + e];
    out[e] = sum;
}

// ---------------------------------------------------------------------------
extern "C" void kernel_launch(void* const* d_in, const int* in_sizes, int n_in,
                              void* d_out, int out_size) {
    const float* hid  = (const float*)d_in[0];
    const float* wqkv = (const float*)d_in[1];
    const float* wo   = (const float*)d_in[2];
    const float* kc   = (const float*)d_in[3];
    const float* vc   = (const float*)d_in[4];
    const int*   pos  = (const int*)d_in[5];
    const int*   btab = (const int*)d_in[6];
    const int*   slen = (const int*)d_in[7];
    float* out = (float*)d_out;

    void *p_qkv_part, *p_attn, *p_out_part;
    cudaGetSymbolAddress(&p_qkv_part, g_qkv_part);
    cudaGetSymbolAddress(&p_attn, g_attn);
    cudaGetSymbolAddress(&p_out_part, g_out_part);

    gemm32<<<dim3(QKV_COLS / 128, KSPLIT), 128>>>(hid, wqkv, (float*)p_qkv_part, QKV_COLS);
    rope_reduce<<<(BATCH * 48 * 64) / 256, 256>>>(pos);
    attn_split<<<dim3(SPLITS, NKV, BATCH), 256>>>(kc, vc, btab, slen);
    combine_splits<<<BATCH * NH, 128>>>();
    gemm32<<<dim3(DMODEL / 128, KSPLIT), 128>>>((const float*)p_attn, wo, (float*)p_out_part, DMODEL);
    final_reduce<<<(BATCH * DMODEL) / 256, 256>>>(out);
}

// round 4
// speedup vs baseline: 1.3058x; 1.2608x over previous
#include <cuda_runtime.h>
#include <math.h>
#include <stdint.h>

#define BATCH   32
#define DMODEL  4096
#define NH      32
#define NKV     8
#define GSZ     4          // NH / NKV
#define HD      128
#define QKV_COLS 6144      // (NH + 2*NKV) * HD
#define PBLOCK  64
#define NBLK    64
#define SPLITS  8
#define SPLIT_LEN 512      // 4096 / SPLITS
#define NSUB    (SPLITS * 8)   // 64 per-warp sub-splits
#define KSPLIT  16
#define KCHUNK  256        // 4096 / KSPLIT

typedef unsigned long long u64;

// -------------------- packed f32x2 helpers (sm_100+) ------------------------
__device__ __forceinline__ u64 ffma2(u64 a, u64 b, u64 c) {
    u64 d;
    asm("fma.rn.f32x2 %0, %1, %2, %3;" : "=l"(d) : "l"(a), "l"(b), "l"(c));
    return d;
}
__device__ __forceinline__ u64 mul2(u64 a, u64 b) {
    u64 d;
    asm("mul.rn.f32x2 %0, %1, %2;" : "=l"(d) : "l"(a), "l"(b));
    return d;
}
__device__ __forceinline__ u64 pack2(float lo, float hi) {
    u64 r;
    asm("mov.b64 %0, {%1, %2};" : "=l"(r) : "f"(lo), "f"(hi));
    return r;
}
__device__ __forceinline__ float2 unpack2(u64 v) {
    float2 f;
    asm("mov.b64 {%0, %1}, %2;" : "=f"(f.x), "=f"(f.y) : "l"(v));
    return f;
}
union F4 {
    float4 f4;
    struct { u64 lo, hi; } u;
};

// ------------------------------ scratch -------------------------------------
__device__ float g_qkv_part[KSPLIT][BATCH][QKV_COLS];   // 12.6 MB
__device__ float g_q[BATCH][NH][HD];                    // prescaled by 1/sqrt(HD)
__device__ float g_knew[BATCH][NKV][HD];
__device__ float g_vnew[BATCH][NKV][HD];
__device__ float g_po[BATCH][NKV][GSZ][NSUB][HD];       // 33.5 MB
__device__ float g_pm[BATCH][NKV][GSZ][NSUB];
__device__ float g_pl[BATCH][NKV][GSZ][NSUB];
__device__ float g_attn[BATCH][NH * HD];
__device__ float g_out_part[KSPLIT][BATCH][DMODEL];     // 8.4 MB

// --------------------- K-split 32-row GEMM:  part[s] = x_chunk @ w_chunk ----
__global__ __launch_bounds__(128) void gemm32(const float* __restrict__ x,
                                              const float* __restrict__ w,
                                              float* __restrict__ part,
                                              int ncols) {
    __shared__ float hs[BATCH][KCHUNK];                 // 32 KB
    const int col = blockIdx.x * 128 + threadIdx.x;
    const int k0  = blockIdx.y * KCHUNK;

    for (int i = threadIdx.x; i < BATCH * (KCHUNK / 4); i += 128) {
        int b  = i >> 6;
        int kk = i & 63;
        ((float4*)hs[b])[kk] = ((const float4*)(x + (size_t)b * DMODEL + k0))[kk];
    }
    __syncthreads();

    u64 acc2[BATCH];
#pragma unroll
    for (int b = 0; b < BATCH; b++) acc2[b] = 0ULL;

    const float* wp = w + (size_t)k0 * ncols + col;
#pragma unroll 2
    for (int k = 0; k < KCHUNK; k += 4) {
        float w0 = wp[(size_t)(k + 0) * ncols];
        float w1 = wp[(size_t)(k + 1) * ncols];
        float w2 = wp[(size_t)(k + 2) * ncols];
        float w3 = wp[(size_t)(k + 3) * ncols];
        u64 w01 = pack2(w0, w1);
        u64 w23 = pack2(w2, w3);
#pragma unroll
        for (int b = 0; b < BATCH; b++) {
            F4 h;
            h.f4 = *(const float4*)&hs[b][k];
            acc2[b] = ffma2(h.u.lo, w01, ffma2(h.u.hi, w23, acc2[b]));
        }
    }
    float* op = part + ((size_t)blockIdx.y * BATCH) * ncols + col;
#pragma unroll
    for (int b = 0; b < BATCH; b++) {
        float2 f = unpack2(acc2[b]);
        op[(size_t)b * ncols] = f.x + f.y;
    }
}

// ----------------- reduce k-splits of QKV + RoPE + split q/k/v --------------
__global__ __launch_bounds__(256) void rope_reduce(const int* __restrict__ pos_ids) {
    int idx = blockIdx.x * 256 + threadIdx.x;
    int j  = idx & 63;
    int hh = (idx >> 6) % 48;
    int b  = idx / (48 * 64);

    int c1 = hh * HD + j;
    int c2 = c1 + 64;
    float x1 = 0.f, x2 = 0.f;
#pragma unroll
    for (int s = 0; s < KSPLIT; s++) {
        x1 += g_qkv_part[s][b][c1];
        x2 += g_qkv_part[s][b][c2];
    }
    if (hh < 40) {
        float invf = exp2f(-(float)j * (19.931568569324174f / 64.f)); // 1e6^(-j/64)
        float ang  = (float)pos_ids[b] * invf;
        float c = cosf(ang), s = sinf(ang);
        float y1 = x1 * c - x2 * s;
        float y2 = x2 * c + x1 * s;
        if (hh < 32) {
            const float sc = 0.08838834764831845f;   // 1/sqrt(128)
            g_q[b][hh][j]      = y1 * sc;
            g_q[b][hh][j + 64] = y2 * sc;
        } else {
            g_knew[b][hh - 32][j]      = y1;
            g_knew[b][hh - 32][j + 64] = y2;
        }
    } else {
        g_vnew[b][hh - 40][j]      = x1;
        g_vnew[b][hh - 40][j + 64] = x2;
    }
}

// ------------------ fused single-pass split-KV flash-decode ------------------
// grid: (SPLITS, NKV, BATCH), block 256 (8 independent warps).
// Each warp: 64 positions (one physical block), K+V streamed interleaved,
// online softmax per 8-lane octet, 2-stage shfl merge, per-warp partial out.
__global__ __launch_bounds__(256) void attn_split(const float* __restrict__ kc,
                                                  const float* __restrict__ vc,
                                                  const int* __restrict__ btab,
                                                  const int* __restrict__ seqlens) {
    const int s   = blockIdx.x;
    const int kvh = blockIdx.y;
    const int b   = blockIdx.z;

    const int t    = threadIdx.x;
    const int w    = t >> 5;
    const int lane = t & 31;
    const int kvlen  = seqlens[b];
    const int newpos = kvlen - 1;

    const int phys = btab[b * NBLK + s * 8 + w];

    const int lsub = lane >> 3;      // position within 4-chunk
    const int dch  = lane & 7;       // 16-dim chunk

    // q for this lane's dim chunk (all GSZ heads), prescaled
    F4 qr[GSZ][4];
#pragma unroll
    for (int g = 0; g < GSZ; g++) {
        const float4* qp = (const float4*)&g_q[b][kvh * GSZ + g][0];
#pragma unroll
        for (int q = 0; q < 4; q++) qr[g][q].f4 = qp[dch * 4 + q];
    }

    float m_[GSZ], l_[GSZ];
    u64 acc2[GSZ][8];
#pragma unroll
    for (int g = 0; g < GSZ; g++) {
        m_[g] = -1e30f;
        l_[g] = 0.f;
#pragma unroll
        for (int j = 0; j < 8; j++) acc2[g][j] = 0ULL;
    }

    const float* kblock = kc + ((size_t)phys * PBLOCK) * NKV * HD + (size_t)kvh * HD;
    const float* vblock = vc + ((size_t)phys * PBLOCK) * NKV * HD + (size_t)kvh * HD;

#pragma unroll 2
    for (int i = 0; i < 16; i++) {
        const int slot = i * 4 + lsub;
        const int gl = s * SPLIT_LEN + w * 64 + slot;
        const float* kp = kblock + (size_t)slot * NKV * HD;
        const float* vp = vblock + (size_t)slot * NKV * HD;
        if (gl == newpos) { kp = &g_knew[b][kvh][0]; vp = &g_vnew[b][kvh][0]; }

        F4 kv[4], vv[4];
#pragma unroll
        for (int q = 0; q < 4; q++) kv[q].f4 = __ldcs(((const float4*)kp) + dch * 4 + q);
#pragma unroll
        for (int q = 0; q < 4; q++) vv[q].f4 = __ldcs(((const float4*)vp) + dch * 4 + q);

        const bool valid = gl < kvlen;
        float sg[GSZ];
#pragma unroll
        for (int g = 0; g < GSZ; g++) {
            u64 a2 = 0ULL;
#pragma unroll
            for (int q = 0; q < 4; q++) {
                a2 = ffma2(qr[g][q].u.lo, kv[q].u.lo, a2);
                a2 = ffma2(qr[g][q].u.hi, kv[q].u.hi, a2);
            }
            float2 f = unpack2(a2);
            sg[g] = f.x + f.y;
        }
        // reduce the dot product within the 8-lane octet
#pragma unroll
        for (int off = 1; off < 8; off <<= 1)
#pragma unroll
            for (int g = 0; g < GSZ; g++)
                sg[g] += __shfl_xor_sync(0xffffffff, sg[g], off);

        // online softmax update (uniform within octet)
#pragma unroll
        for (int g = 0; g < GSZ; g++) {
            float sv = valid ? sg[g] : -1e30f;
            float mold = m_[g];
            float mn = fmaxf(mold, sv);
            float p = valid ? __expf(sv - mn) : 0.f;
            if (mn != mold) {
                float corr = __expf(mold - mn);
                u64 c2 = pack2(corr, corr);
                l_[g] = l_[g] * corr + p;
#pragma unroll
                for (int j = 0; j < 8; j++) acc2[g][j] = mul2(acc2[g][j], c2);
                m_[g] = mn;
            } else {
                l_[g] += p;
            }
            u64 p2 = pack2(p, p);
#pragma unroll
            for (int q = 0; q < 4; q++) {
                acc2[g][2 * q]     = ffma2(p2, vv[q].u.lo, acc2[g][2 * q]);
                acc2[g][2 * q + 1] = ffma2(p2, vv[q].u.hi, acc2[g][2 * q + 1]);
            }
        }
    }

    // merge the 4 position-streams (lane bits 3,4) with flash-merge math
#pragma unroll
    for (int off = 8; off <= 16; off <<= 1) {
#pragma unroll
        for (int g = 0; g < GSZ; g++) {
            float mo = __shfl_xor_sync(0xffffffff, m_[g], off);
            float lo = __shfl_xor_sync(0xffffffff, l_[g], off);
            float mn = fmaxf(m_[g], mo);
            float a  = __expf(m_[g] - mn);
            float bb = __expf(mo - mn);
            l_[g] = l_[g] * a + lo * bb;
            m_[g] = mn;
#pragma unroll
            for (int j = 0; j < 8; j++) {
                float2 f = unpack2(acc2[g][j]);
                float fx = __shfl_xor_sync(0xffffffff, f.x, off);
                float fy = __shfl_xor_sync(0xffffffff, f.y, off);
                f.x = f.x * a + fx * bb;
                f.y = f.y * a + fy * bb;
                acc2[g][j] = pack2(f.x, f.y);
            }
        }
    }

    // write per-warp partial (sub-split s*8+w)
    const int sub = s * 8 + w;
    if (lsub == 0) {
#pragma unroll
        for (int g = 0; g < GSZ; g++) {
            float4* dst = (float4*)&g_po[b][kvh][g][sub][0];
#pragma unroll
            for (int q = 0; q < 4; q++) {
                F4 o;
                o.u.lo = acc2[g][2 * q];
                o.u.hi = acc2[g][2 * q + 1];
                dst[dch * 4 + q] = o.f4;
            }
        }
        if (dch == 0) {
#pragma unroll
            for (int g = 0; g < GSZ; g++) {
                g_pm[b][kvh][g][sub] = m_[g];
                g_pl[b][kvh][g][sub] = l_[g];
            }
        }
    }
}

// ----------------------- combine sub-split partials --------------------------
// grid: BATCH*NH = 1024 blocks, 128 threads (one per d)
__global__ __launch_bounds__(128) void combine_splits() {
    const int bh = blockIdx.x;
    const int b = bh >> 5, h = bh & 31;
    const int kvh = h >> 2, g = h & 3;
    const int d = threadIdx.x;

    float m = -1e30f;
#pragma unroll 8
    for (int s = 0; s < NSUB; s++) m = fmaxf(m, g_pm[b][kvh][g][s]);
    float denom = 0.f, o = 0.f;
#pragma unroll 4
    for (int s = 0; s < NSUB; s++) {
        float e = __expf(g_pm[b][kvh][g][s] - m);
        denom += e * g_pl[b][kvh][g][s];
        o += e * g_po[b][kvh][g][s][d];
    }
    g_attn[b][h * HD + d] = o / denom;
}

// ----------------------- final k-split reduce -------------------------------
__global__ __launch_bounds__(256) void final_reduce(float* __restrict__ out) {
    int e = blockIdx.x * 256 + threadIdx.x;        // over 32*4096
    const float* p = &g_out_part[0][0][0];
    float sum = 0.f;
#pragma unroll
    for (int s = 0; s < KSPLIT; s++) sum += p[(size_t)s * BATCH * DMODEL + e];
    out[e] = sum;
}

// ---------------------------------------------------------------------------
extern "C" void kernel_launch(void* const* d_in, const int* in_sizes, int n_in,
                              void* d_out, int out_size) {
    const float* hid  = (const float*)d_in[0];
    const float* wqkv = (const float*)d_in[1];
    const float* wo   = (const float*)d_in[2];
    const float* kc   = (const float*)d_in[3];
    const float* vc   = (const float*)d_in[4];
    const int*   pos  = (const int*)d_in[5];
    const int*   btab = (const int*)d_in[6];
    const int*   slen = (const int*)d_in[7];
    float* out = (float*)d_out;

    void *p_qkv_part, *p_attn, *p_out_part;
    cudaGetSymbolAddress(&p_qkv_part, g_qkv_part);
    cudaGetSymbolAddress(&p_attn, g_attn);
    cudaGetSymbolAddress(&p_out_part, g_out_part);

    gemm32<<<dim3(QKV_COLS / 128, KSPLIT), 128>>>(hid, wqkv, (float*)p_qkv_part, QKV_COLS);
    rope_reduce<<<(BATCH * 48 * 64) / 256, 256>>>(pos);
    attn_split<<<dim3(SPLITS, NKV, BATCH), 256>>>(kc, vc, btab, slen);
    combine_splits<<<BATCH * NH, 128>>>();
    gemm32<<<dim3(DMODEL / 128, KSPLIT), 128>>>((const float*)p_attn, wo, (float*)p_out_part, DMODEL);
    final_reduce<<<(BATCH * DMODEL) / 256, 256>>>(out);
}

// round 5
// speedup vs baseline: 1.4422x; 1.1044x over previous
#include <cuda_runtime.h>
#include <math.h>
#include <stdint.h>

#define BATCH   32
#define DMODEL  4096
#define NH      32
#define NKV     8
#define GSZ     4          // NH / NKV
#define HD      128
#define QKV_COLS 6144      // (NH + 2*NKV) * HD
#define PBLOCK  64
#define NBLK    64
#define SPLITS  8
#define SPLIT_LEN 512      // 4096 / SPLITS
#define NSUB    (SPLITS * 8)   // 64 per-warp sub-splits
#define KSPLIT  16
#define KCHUNK  256        // 4096 / KSPLIT

typedef unsigned long long u64;

// -------------------- packed f32x2 helpers (sm_100+) ------------------------
__device__ __forceinline__ u64 ffma2(u64 a, u64 b, u64 c) {
    u64 d;
    asm("fma.rn.f32x2 %0, %1, %2, %3;" : "=l"(d) : "l"(a), "l"(b), "l"(c));
    return d;
}
__device__ __forceinline__ u64 pack2(float lo, float hi) {
    u64 r;
    asm("mov.b64 %0, {%1, %2};" : "=l"(r) : "f"(lo), "f"(hi));
    return r;
}
__device__ __forceinline__ float2 unpack2(u64 v) {
    float2 f;
    asm("mov.b64 {%0, %1}, %2;" : "=f"(f.x), "=f"(f.y) : "l"(v));
    return f;
}
union F4 {
    float4 f4;
    struct { u64 lo, hi; } u;
};

// ------------------------------ scratch -------------------------------------
__device__ float g_qkv_part[KSPLIT][BATCH][QKV_COLS];   // 12.6 MB
__device__ float g_q[BATCH][NH][HD];                    // prescaled by 1/sqrt(HD)
__device__ float g_knew[BATCH][NKV][HD];
__device__ float g_vnew[BATCH][NKV][HD];
__device__ float g_po[BATCH][NKV][GSZ][NSUB][HD];       // 33.5 MB
__device__ float g_pm[BATCH][NKV][GSZ][NSUB];
__device__ float g_pl[BATCH][NKV][GSZ][NSUB];
__device__ float g_attn[BATCH][NH * HD];
__device__ float g_out_part[KSPLIT][BATCH][DMODEL];     // 8.4 MB

// --------------------- K-split 32-row GEMM:  part[s] = x_chunk @ w_chunk ----
__global__ __launch_bounds__(128) void gemm32(const float* __restrict__ x,
                                              const float* __restrict__ w,
                                              float* __restrict__ part,
                                              int ncols) {
    __shared__ float hs[BATCH][KCHUNK];                 // 32 KB
    const int col = blockIdx.x * 128 + threadIdx.x;
    const int k0  = blockIdx.y * KCHUNK;

    for (int i = threadIdx.x; i < BATCH * (KCHUNK / 4); i += 128) {
        int b  = i >> 6;
        int kk = i & 63;
        ((float4*)hs[b])[kk] = ((const float4*)(x + (size_t)b * DMODEL + k0))[kk];
    }
    __syncthreads();

    u64 acc2[BATCH];
#pragma unroll
    for (int b = 0; b < BATCH; b++) acc2[b] = 0ULL;

    const float* wp = w + (size_t)k0 * ncols + col;
#pragma unroll 2
    for (int k = 0; k < KCHUNK; k += 4) {
        float w0 = wp[(size_t)(k + 0) * ncols];
        float w1 = wp[(size_t)(k + 1) * ncols];
        float w2 = wp[(size_t)(k + 2) * ncols];
        float w3 = wp[(size_t)(k + 3) * ncols];
        u64 w01 = pack2(w0, w1);
        u64 w23 = pack2(w2, w3);
#pragma unroll
        for (int b = 0; b < BATCH; b++) {
            F4 h;
            h.f4 = *(const float4*)&hs[b][k];
            acc2[b] = ffma2(h.u.lo, w01, ffma2(h.u.hi, w23, acc2[b]));
        }
    }
    float* op = part + ((size_t)blockIdx.y * BATCH) * ncols + col;
#pragma unroll
    for (int b = 0; b < BATCH; b++) {
        float2 f = unpack2(acc2[b]);
        op[(size_t)b * ncols] = f.x + f.y;
    }
}

// ----------------- reduce k-splits of QKV + RoPE + split q/k/v --------------
__global__ __launch_bounds__(256) void rope_reduce(const int* __restrict__ pos_ids) {
    int idx = blockIdx.x * 256 + threadIdx.x;
    int j  = idx & 63;
    int hh = (idx >> 6) % 48;
    int b  = idx / (48 * 64);

    int c1 = hh * HD + j;
    int c2 = c1 + 64;
    float x1 = 0.f, x2 = 0.f;
#pragma unroll
    for (int s = 0; s < KSPLIT; s++) {
        x1 += g_qkv_part[s][b][c1];
        x2 += g_qkv_part[s][b][c2];
    }
    if (hh < 40) {
        float invf = exp2f(-(float)j * (19.931568569324174f / 64.f)); // 1e6^(-j/64)
        float ang  = (float)pos_ids[b] * invf;
        float c = cosf(ang), s = sinf(ang);
        float y1 = x1 * c - x2 * s;
        float y2 = x2 * c + x1 * s;
        if (hh < 32) {
            const float sc = 0.08838834764831845f;   // 1/sqrt(128)
            g_q[b][hh][j]      = y1 * sc;
            g_q[b][hh][j + 64] = y2 * sc;
        } else {
            g_knew[b][hh - 32][j]      = y1;
            g_knew[b][hh - 32][j + 64] = y2;
        }
    } else {
        g_vnew[b][hh - 40][j]      = x1;
        g_vnew[b][hh - 40][j + 64] = x2;
    }
}

// ------------- per-warp two-phase split-KV flash-decode (no CTA sync) --------
// grid: (SPLITS, NKV, BATCH), block 256 (8 fully independent warps).
// Phase A: stream K, bank scores in per-warp smem (branchless loop body).
// Phase B: warp max + exp + l (once).
// Phase C: stream V with plain p*v accumulation (branchless, exp-free loop).
__global__ __launch_bounds__(256) void attn_split(const float* __restrict__ kc,
                                                  const float* __restrict__ vc,
                                                  const int* __restrict__ btab,
                                                  const int* __restrict__ seqlens) {
    const int s   = blockIdx.x;
    const int kvh = blockIdx.y;
    const int b   = blockIdx.z;

    __shared__ float ps[8][GSZ][PBLOCK];   // 8 KB: per-warp scores then probs

    const int t    = threadIdx.x;
    const int w    = t >> 5;
    const int lane = t & 31;
    const int kvlen  = seqlens[b];
    const int newpos = kvlen - 1;

    const int phys = btab[b * NBLK + s * 8 + w];
    const int lsub = lane >> 3;      // position within 4-group
    const int dch  = lane & 7;       // 16-dim chunk

    const float* kblock = kc + ((size_t)phys * PBLOCK) * NKV * HD + (size_t)kvh * HD;
    const float* vblock = vc + ((size_t)phys * PBLOCK) * NKV * HD + (size_t)kvh * HD;

    // ---------------- phase A: scores -> smem ----------------
    {
        F4 qr[GSZ][4];
#pragma unroll
        for (int g = 0; g < GSZ; g++) {
            const float4* qp = (const float4*)&g_q[b][kvh * GSZ + g][0];
#pragma unroll
            for (int q = 0; q < 4; q++) qr[g][q].f4 = qp[dch * 4 + q];
        }

        float mloc[GSZ];
#pragma unroll
        for (int g = 0; g < GSZ; g++) mloc[g] = -1e30f;

#pragma unroll 2
        for (int i = 0; i < 16; i++) {
            const int slot = i * 4 + lsub;
            const int gl = s * SPLIT_LEN + w * 64 + slot;
            const float* kp = kblock + (size_t)slot * NKV * HD;
            if (gl == newpos) kp = &g_knew[b][kvh][0];

            F4 kv[4];
#pragma unroll
            for (int q = 0; q < 4; q++) kv[q].f4 = __ldcs(((const float4*)kp) + dch * 4 + q);

            float sg[GSZ];
#pragma unroll
            for (int g = 0; g < GSZ; g++) {
                u64 a2 = 0ULL;
#pragma unroll
                for (int q = 0; q < 4; q++) {
                    a2 = ffma2(qr[g][q].u.lo, kv[q].u.lo, a2);
                    a2 = ffma2(qr[g][q].u.hi, kv[q].u.hi, a2);
                }
                float2 f = unpack2(a2);
                sg[g] = f.x + f.y;
            }
#pragma unroll
            for (int off = 1; off < 8; off <<= 1)
#pragma unroll
                for (int g = 0; g < GSZ; g++)
                    sg[g] += __shfl_xor_sync(0xffffffff, sg[g], off);

            const bool valid = gl < kvlen;
            if (dch == 0) {
#pragma unroll
                for (int g = 0; g < GSZ; g++) {
                    float sv = valid ? sg[g] : -1e30f;
                    ps[w][g][slot] = sv;
                    mloc[g] = fmaxf(mloc[g], sv);
                }
            }
        }
        // warp-wide max (only dch==0 lanes hold real data; others -1e30)
#pragma unroll
        for (int off = 16; off >= 1; off >>= 1)
#pragma unroll
            for (int g = 0; g < GSZ; g++)
                mloc[g] = fmaxf(mloc[g], __shfl_xor_sync(0xffffffff, mloc[g], off));
        __syncwarp();

        // ---------------- phase B: exp + l ----------------
        float l_[GSZ];
#pragma unroll
        for (int g = 0; g < GSZ; g++) {
            float p0 = __expf(ps[w][g][lane]      - mloc[g]);
            float p1 = __expf(ps[w][g][lane + 32] - mloc[g]);
            ps[w][g][lane]      = p0;
            ps[w][g][lane + 32] = p1;
            float sum = p0 + p1;
#pragma unroll
            for (int off = 16; off >= 1; off >>= 1)
                sum += __shfl_xor_sync(0xffffffff, sum, off);
            l_[g] = sum;
        }
        __syncwarp();

        const int sub = s * 8 + w;
        if (lane == 0) {
#pragma unroll
            for (int g = 0; g < GSZ; g++) {
                g_pm[b][kvh][g][sub] = mloc[g];
                g_pl[b][kvh][g][sub] = l_[g];
            }
        }
    }

    // ---------------- phase C: p @ V (branchless, exp-free) ----------------
    u64 acc2[GSZ][8];
#pragma unroll
    for (int g = 0; g < GSZ; g++)
#pragma unroll
        for (int j = 0; j < 8; j++) acc2[g][j] = 0ULL;

#pragma unroll 2
    for (int i = 0; i < 16; i++) {
        const int slot = i * 4 + lsub;
        const int gl = s * SPLIT_LEN + w * 64 + slot;
        const float* vp = vblock + (size_t)slot * NKV * HD;
        if (gl == newpos) vp = &g_vnew[b][kvh][0];

        F4 vv[4];
#pragma unroll
        for (int q = 0; q < 4; q++) vv[q].f4 = __ldcs(((const float4*)vp) + dch * 4 + q);

#pragma unroll
        for (int g = 0; g < GSZ; g++) {
            float p = ps[w][g][slot];             // smem broadcast within octet
            u64 p2 = pack2(p, p);
#pragma unroll
            for (int q = 0; q < 4; q++) {
                acc2[g][2 * q]     = ffma2(p2, vv[q].u.lo, acc2[g][2 * q]);
                acc2[g][2 * q + 1] = ffma2(p2, vv[q].u.hi, acc2[g][2 * q + 1]);
            }
        }
    }

    // merge the 4 position-groups (lane bits 3,4): plain adds (shared max)
#pragma unroll
    for (int off = 8; off <= 16; off <<= 1) {
#pragma unroll
        for (int g = 0; g < GSZ; g++)
#pragma unroll
            for (int j = 0; j < 8; j++) {
                float2 f = unpack2(acc2[g][j]);
                f.x += __shfl_xor_sync(0xffffffff, f.x, off);
                f.y += __shfl_xor_sync(0xffffffff, f.y, off);
                acc2[g][j] = pack2(f.x, f.y);
            }
    }

    const int sub = s * 8 + w;
    if (lsub == 0) {
#pragma unroll
        for (int g = 0; g < GSZ; g++) {
            float4* dst = (float4*)&g_po[b][kvh][g][sub][0];
#pragma unroll
            for (int q = 0; q < 4; q++) {
                F4 o;
                o.u.lo = acc2[g][2 * q];
                o.u.hi = acc2[g][2 * q + 1];
                dst[dch * 4 + q] = o.f4;
            }
        }
    }
}

// ----------------------- combine sub-split partials --------------------------
// grid: BATCH*NH = 1024 blocks, 128 threads (one per d)
__global__ __launch_bounds__(128) void combine_splits() {
    const int bh = blockIdx.x;
    const int b = bh >> 5, h = bh & 31;
    const int kvh = h >> 2, g = h & 3;
    const int d = threadIdx.x;

    float m = -1e30f;
#pragma unroll 8
    for (int s = 0; s < NSUB; s++) m = fmaxf(m, g_pm[b][kvh][g][s]);
    float denom = 0.f, o = 0.f;
#pragma unroll 4
    for (int s = 0; s < NSUB; s++) {
        float e = __expf(g_pm[b][kvh][g][s] - m);
        denom += e * g_pl[b][kvh][g][s];
        o += e * g_po[b][kvh][g][s][d];
    }
    g_attn[b][h * HD + d] = o / denom;
}

// ----------------------- final k-split reduce -------------------------------
__global__ __launch_bounds__(256) void final_reduce(float* __restrict__ out) {
    int e = blockIdx.x * 256 + threadIdx.x;        // over 32*4096
    const float* p = &g_out_part[0][0][0];
    float sum = 0.f;
#pragma unroll
    for (int s = 0; s < KSPLIT; s++) sum += p[(size_t)s * BATCH * DMODEL + e];
    out[e] = sum;
}

// ---------------------------------------------------------------------------
extern "C" void kernel_launch(void* const* d_in, const int* in_sizes, int n_in,
                              void* d_out, int out_size) {
    const float* hid  = (const float*)d_in[0];
    const float* wqkv = (const float*)d_in[1];
    const float* wo   = (const float*)d_in[2];
    const float* kc   = (const float*)d_in[3];
    const float* vc   = (const float*)d_in[4];
    const int*   pos  = (const int*)d_in[5];
    const int*   btab = (const int*)d_in[6];
    const int*   slen = (const int*)d_in[7];
    float* out = (float*)d_out;

    void *p_qkv_part, *p_attn, *p_out_part;
    cudaGetSymbolAddress(&p_qkv_part, g_qkv_part);
    cudaGetSymbolAddress(&p_attn, g_attn);
    cudaGetSymbolAddress(&p_out_part, g_out_part);

    gemm32<<<dim3(QKV_COLS / 128, KSPLIT), 128>>>(hid, wqkv, (float*)p_qkv_part, QKV_COLS);
    rope_reduce<<<(BATCH * 48 * 64) / 256, 256>>>(pos);
    attn_split<<<dim3(SPLITS, NKV, BATCH), 256>>>(kc, vc, btab, slen);
    combine_splits<<<BATCH * NH, 128>>>();
    gemm32<<<dim3(DMODEL / 128, KSPLIT), 128>>>((const float*)p_attn, wo, (float*)p_out_part, DMODEL);
    final_reduce<<<(BATCH * DMODEL) / 256, 256>>>(out);
}

// round 6
// speedup vs baseline: 1.4880x; 1.0318x over previous
#include <cuda_runtime.h>
#include <math.h>
#include <stdint.h>

#define BATCH   32
#define DMODEL  4096
#define NH      32
#define NKV     8
#define GSZ     4          // NH / NKV
#define HD      128
#define QKV_COLS 6144      // (NH + 2*NKV) * HD
#define PBLOCK  64
#define NBLK    64
#define SPLITS  8
#define SPLIT_LEN 512      // 4096 / SPLITS
#define NSUB    SPLITS     // per-CTA merged partials
#define KSPLIT  16
#define KCHUNK  256        // 4096 / KSPLIT

typedef unsigned long long u64;

// -------------------- packed f32x2 helpers (sm_100+) ------------------------
__device__ __forceinline__ u64 ffma2(u64 a, u64 b, u64 c) {
    u64 d;
    asm("fma.rn.f32x2 %0, %1, %2, %3;" : "=l"(d) : "l"(a), "l"(b), "l"(c));
    return d;
}
__device__ __forceinline__ u64 pack2(float lo, float hi) {
    u64 r;
    asm("mov.b64 %0, {%1, %2};" : "=l"(r) : "f"(lo), "f"(hi));
    return r;
}
__device__ __forceinline__ float2 unpack2(u64 v) {
    float2 f;
    asm("mov.b64 {%0, %1}, %2;" : "=f"(f.x), "=f"(f.y) : "l"(v));
    return f;
}
union F4 {
    float4 f4;
    struct { u64 lo, hi; } u;
};

// ------------------------------ scratch -------------------------------------
__device__ float g_qkv_part[KSPLIT][BATCH][QKV_COLS];   // 12.6 MB
__device__ float g_q[BATCH][NH][HD];                    // prescaled by 1/sqrt(HD)
__device__ float g_knew[BATCH][NKV][HD];
__device__ float g_vnew[BATCH][NKV][HD];
__device__ float g_po[BATCH][NKV][GSZ][NSUB][HD];       // 4.2 MB
__device__ float g_pm[BATCH][NKV][GSZ][NSUB];
__device__ float g_pl[BATCH][NKV][GSZ][NSUB];
__device__ float g_attn[BATCH][NH * HD];
__device__ float g_out_part[KSPLIT][BATCH][DMODEL];     // 8.4 MB

// --------------------- K-split 32-row GEMM:  part[s] = x_chunk @ w_chunk ----
__global__ __launch_bounds__(128) void gemm32(const float* __restrict__ x,
                                              const float* __restrict__ w,
                                              float* __restrict__ part,
                                              int ncols) {
    __shared__ float hs[BATCH][KCHUNK];                 // 32 KB
    const int col = blockIdx.x * 128 + threadIdx.x;
    const int k0  = blockIdx.y * KCHUNK;

    for (int i = threadIdx.x; i < BATCH * (KCHUNK / 4); i += 128) {
        int b  = i >> 6;
        int kk = i & 63;
        ((float4*)hs[b])[kk] = ((const float4*)(x + (size_t)b * DMODEL + k0))[kk];
    }
    __syncthreads();

    u64 acc2[BATCH];
#pragma unroll
    for (int b = 0; b < BATCH; b++) acc2[b] = 0ULL;

    const float* wp = w + (size_t)k0 * ncols + col;
#pragma unroll 2
    for (int k = 0; k < KCHUNK; k += 4) {
        float w0 = wp[(size_t)(k + 0) * ncols];
        float w1 = wp[(size_t)(k + 1) * ncols];
        float w2 = wp[(size_t)(k + 2) * ncols];
        float w3 = wp[(size_t)(k + 3) * ncols];
        u64 w01 = pack2(w0, w1);
        u64 w23 = pack2(w2, w3);
#pragma unroll
        for (int b = 0; b < BATCH; b++) {
            F4 h;
            h.f4 = *(const float4*)&hs[b][k];
            acc2[b] = ffma2(h.u.lo, w01, ffma2(h.u.hi, w23, acc2[b]));
        }
    }
    float* op = part + ((size_t)blockIdx.y * BATCH) * ncols + col;
#pragma unroll
    for (int b = 0; b < BATCH; b++) {
        float2 f = unpack2(acc2[b]);
        op[(size_t)b * ncols] = f.x + f.y;
    }
}

// ----------------- reduce k-splits of QKV + RoPE + split q/k/v --------------
__global__ __launch_bounds__(256) void rope_reduce(const int* __restrict__ pos_ids) {
    int idx = blockIdx.x * 256 + threadIdx.x;
    int j  = idx & 63;
    int hh = (idx >> 6) % 48;
    int b  = idx / (48 * 64);

    int c1 = hh * HD + j;
    int c2 = c1 + 64;
    float x1 = 0.f, x2 = 0.f;
#pragma unroll
    for (int s = 0; s < KSPLIT; s++) {
        x1 += g_qkv_part[s][b][c1];
        x2 += g_qkv_part[s][b][c2];
    }
    if (hh < 40) {
        float invf = exp2f(-(float)j * (19.931568569324174f / 64.f)); // 1e6^(-j/64)
        float ang  = (float)pos_ids[b] * invf;
        float c = cosf(ang), s = sinf(ang);
        float y1 = x1 * c - x2 * s;
        float y2 = x2 * c + x1 * s;
        if (hh < 32) {
            const float sc = 0.08838834764831845f;   // 1/sqrt(128)
            g_q[b][hh][j]      = y1 * sc;
            g_q[b][hh][j + 64] = y2 * sc;
        } else {
            g_knew[b][hh - 32][j]      = y1;
            g_knew[b][hh - 32][j + 64] = y2;
        }
    } else {
        g_vnew[b][hh - 40][j]      = x1;
        g_vnew[b][hh - 40][j + 64] = x2;
    }
}

// ------------- per-warp two-phase split-KV flash-decode ----------------------
// grid: (SPLITS, NKV, BATCH), block 256 (8 warps).
// Phase A: per-warp K stream (octet dot products), scores -> smem float4.
// Phase B: per-warp max + exp + l.
// Phase C: per-warp V stream, all 32 lanes on one position (float4 = 128 d),
//          acc = GSZ x float4 regs, no cross-lane merge.
// Epilogue: one __syncthreads, smem flash-merge of the 8 warps -> 1 partial.
__global__ __launch_bounds__(256, 2) void attn_split(const float* __restrict__ kc,
                                                     const float* __restrict__ vc,
                                                     const int* __restrict__ btab,
                                                     const int* __restrict__ seqlens) {
    const int s   = blockIdx.x;
    const int kvh = blockIdx.y;
    const int b   = blockIdx.z;

    __shared__ float4 ps4[8][PBLOCK];       // 8 KB: per-warp scores/probs (g-packed)
    __shared__ float  red[8][GSZ][HD];      // 16 KB: per-warp V partials
    __shared__ float  sm_m[8][GSZ], sm_l[8][GSZ];

    const int t    = threadIdx.x;
    const int w    = t >> 5;
    const int lane = t & 31;
    const int kvlen  = seqlens[b];
    const int newpos = kvlen - 1;

    const int phys = btab[b * NBLK + s * 8 + w];
    const int lsub = lane >> 3;      // octet index (position group)
    const int dch  = lane & 7;       // 16-dim chunk within octet

    const float* kblock = kc + ((size_t)phys * PBLOCK) * NKV * HD + (size_t)kvh * HD;
    const float* vblock = vc + ((size_t)phys * PBLOCK) * NKV * HD + (size_t)kvh * HD;
    const int base = s * SPLIT_LEN + w * 64;

    float mloc[GSZ];
    // ---------------- phase A: scores -> smem ----------------
    {
        F4 qr[GSZ][4];
#pragma unroll
        for (int g = 0; g < GSZ; g++) {
            const float4* qp = (const float4*)&g_q[b][kvh * GSZ + g][0];
#pragma unroll
            for (int q = 0; q < 4; q++) qr[g][q].f4 = qp[dch * 4 + q];
        }
#pragma unroll
        for (int g = 0; g < GSZ; g++) mloc[g] = -1e30f;

#pragma unroll 2
        for (int i = 0; i < 16; i++) {
            const int slot = i * 4 + lsub;
            const int gl = base + slot;
            const float* kp = kblock + (size_t)slot * NKV * HD;
            if (gl == newpos) kp = &g_knew[b][kvh][0];

            F4 kv[4];
#pragma unroll
            for (int q = 0; q < 4; q++) kv[q].f4 = __ldcs(((const float4*)kp) + dch * 4 + q);

            float sg[GSZ];
#pragma unroll
            for (int g = 0; g < GSZ; g++) {
                u64 a2 = 0ULL;
#pragma unroll
                for (int q = 0; q < 4; q++) {
                    a2 = ffma2(qr[g][q].u.lo, kv[q].u.lo, a2);
                    a2 = ffma2(qr[g][q].u.hi, kv[q].u.hi, a2);
                }
                float2 f = unpack2(a2);
                sg[g] = f.x + f.y;
            }
#pragma unroll
            for (int off = 1; off < 8; off <<= 1)
#pragma unroll
                for (int g = 0; g < GSZ; g++)
                    sg[g] += __shfl_xor_sync(0xffffffff, sg[g], off);

            if (dch == 0) {
                const bool valid = gl < kvlen;
                float4 sv;
                sv.x = valid ? sg[0] : -1e30f;
                sv.y = valid ? sg[1] : -1e30f;
                sv.z = valid ? sg[2] : -1e30f;
                sv.w = valid ? sg[3] : -1e30f;
                ps4[w][slot] = sv;
                mloc[0] = fmaxf(mloc[0], sv.x);
                mloc[1] = fmaxf(mloc[1], sv.y);
                mloc[2] = fmaxf(mloc[2], sv.z);
                mloc[3] = fmaxf(mloc[3], sv.w);
            }
        }
#pragma unroll
        for (int off = 16; off >= 1; off >>= 1)
#pragma unroll
            for (int g = 0; g < GSZ; g++)
                mloc[g] = fmaxf(mloc[g], __shfl_xor_sync(0xffffffff, mloc[g], off));
        __syncwarp();
    }

    // ---------------- phase B: exp + l ----------------
    {
        float4 s0 = ps4[w][lane];
        float4 s1 = ps4[w][lane + 32];
        float4 p0, p1;
        p0.x = __expf(s0.x - mloc[0]); p1.x = __expf(s1.x - mloc[0]);
        p0.y = __expf(s0.y - mloc[1]); p1.y = __expf(s1.y - mloc[1]);
        p0.z = __expf(s0.z - mloc[2]); p1.z = __expf(s1.z - mloc[2]);
        p0.w = __expf(s0.w - mloc[3]); p1.w = __expf(s1.w - mloc[3]);
        ps4[w][lane] = p0;
        ps4[w][lane + 32] = p1;
        float l0 = p0.x + p1.x, l1 = p0.y + p1.y;
        float l2 = p0.z + p1.z, l3 = p0.w + p1.w;
#pragma unroll
        for (int off = 16; off >= 1; off >>= 1) {
            l0 += __shfl_xor_sync(0xffffffff, l0, off);
            l1 += __shfl_xor_sync(0xffffffff, l1, off);
            l2 += __shfl_xor_sync(0xffffffff, l2, off);
            l3 += __shfl_xor_sync(0xffffffff, l3, off);
        }
        if (lane == 0) {
            sm_m[w][0] = mloc[0]; sm_m[w][1] = mloc[1];
            sm_m[w][2] = mloc[2]; sm_m[w][3] = mloc[3];
            sm_l[w][0] = l0; sm_l[w][1] = l1; sm_l[w][2] = l2; sm_l[w][3] = l3;
        }
        __syncwarp();
    }

    // -------- phase C: V stream, one position per iter, all lanes ----------
    {
        u64 acc2[GSZ][2];
#pragma unroll
        for (int g = 0; g < GSZ; g++) { acc2[g][0] = 0ULL; acc2[g][1] = 0ULL; }

#pragma unroll 8
        for (int slot = 0; slot < 64; slot++) {
            const int gl = base + slot;
            const float* vp = vblock + (size_t)slot * NKV * HD;
            if (gl == newpos) vp = &g_vnew[b][kvh][0];
            F4 v4;
            v4.f4 = __ldcs(((const float4*)vp) + lane);
            float4 p4 = ps4[w][slot];            // smem broadcast
            u64 pa = pack2(p4.x, p4.x);
            u64 pb = pack2(p4.y, p4.y);
            u64 pc = pack2(p4.z, p4.z);
            u64 pd = pack2(p4.w, p4.w);
            acc2[0][0] = ffma2(pa, v4.u.lo, acc2[0][0]);
            acc2[0][1] = ffma2(pa, v4.u.hi, acc2[0][1]);
            acc2[1][0] = ffma2(pb, v4.u.lo, acc2[1][0]);
            acc2[1][1] = ffma2(pb, v4.u.hi, acc2[1][1]);
            acc2[2][0] = ffma2(pc, v4.u.lo, acc2[2][0]);
            acc2[2][1] = ffma2(pc, v4.u.hi, acc2[2][1]);
            acc2[3][0] = ffma2(pd, v4.u.lo, acc2[3][0]);
            acc2[3][1] = ffma2(pd, v4.u.hi, acc2[3][1]);
        }
#pragma unroll
        for (int g = 0; g < GSZ; g++) {
            F4 o;
            o.u.lo = acc2[g][0];
            o.u.hi = acc2[g][1];
            ((float4*)&red[w][g][0])[lane] = o.f4;
        }
    }
    __syncthreads();

    // -------- epilogue: flash-merge the 8 warps' partials -> one ----------
    // 256 threads over GSZ*HD = 512 elements: 2 per thread
#pragma unroll
    for (int rep = 0; rep < 2; rep++) {
        int idx = t + rep * 256;
        int g = idx >> 7, d = idx & 127;
        float M = sm_m[0][g];
#pragma unroll
        for (int ww = 1; ww < 8; ww++) M = fmaxf(M, sm_m[ww][g]);
        float o = 0.f;
#pragma unroll
        for (int ww = 0; ww < 8; ww++)
            o += __expf(sm_m[ww][g] - M) * red[ww][g][d];
        g_po[b][kvh][g][s][d] = o;
        if (d == 0) {
            float L = 0.f;
#pragma unroll
            for (int ww = 0; ww < 8; ww++)
                L += __expf(sm_m[ww][g] - M) * sm_l[ww][g];
            g_pm[b][kvh][g][s] = M;
            g_pl[b][kvh][g][s] = L;
        }
    }
}

// ----------------------- combine split partials -----------------------------
// grid: BATCH*NH = 1024 blocks, 128 threads (one per d)
__global__ __launch_bounds__(128) void combine_splits() {
    const int bh = blockIdx.x;
    const int b = bh >> 5, h = bh & 31;
    const int kvh = h >> 2, g = h & 3;
    const int d = threadIdx.x;

    float m = -1e30f;
#pragma unroll
    for (int s = 0; s < NSUB; s++) m = fmaxf(m, g_pm[b][kvh][g][s]);
    float denom = 0.f, o = 0.f;
#pragma unroll
    for (int s = 0; s < NSUB; s++) {
        float e = __expf(g_pm[b][kvh][g][s] - m);
        denom += e * g_pl[b][kvh][g][s];
        o += e * g_po[b][kvh][g][s][d];
    }
    g_attn[b][h * HD + d] = o / denom;
}

// ----------------------- final k-split reduce -------------------------------
__global__ __launch_bounds__(256) void final_reduce(float* __restrict__ out) {
    int e = blockIdx.x * 256 + threadIdx.x;        // over 32*4096
    const float* p = &g_out_part[0][0][0];
    float sum = 0.f;
#pragma unroll
    for (int s = 0; s < KSPLIT; s++) sum += p[(size_t)s * BATCH * DMODEL + e];
    out[e] = sum;
}

// ---------------------------------------------------------------------------
extern "C" void kernel_launch(void* const* d_in, const int* in_sizes, int n_in,
                              void* d_out, int out_size) {
    const float* hid  = (const float*)d_in[0];
    const float* wqkv = (const float*)d_in[1];
    const float* wo   = (const float*)d_in[2];
    const float* kc   = (const float*)d_in[3];
    const float* vc   = (const float*)d_in[4];
    const int*   pos  = (const int*)d_in[5];
    const int*   btab = (const int*)d_in[6];
    const int*   slen = (const int*)d_in[7];
    float* out = (float*)d_out;

    void *p_qkv_part, *p_attn, *p_out_part;
    cudaGetSymbolAddress(&p_qkv_part, g_qkv_part);
    cudaGetSymbolAddress(&p_attn, g_attn);
    cudaGetSymbolAddress(&p_out_part, g_out_part);

    gemm32<<<dim3(QKV_COLS / 128, KSPLIT), 128>>>(hid, wqkv, (float*)p_qkv_part, QKV_COLS);
    rope_reduce<<<(BATCH * 48 * 64) / 256, 256>>>(pos);
    attn_split<<<dim3(SPLITS, NKV, BATCH), 256>>>(kc, vc, btab, slen);
    combine_splits<<<BATCH * NH, 128>>>();
    gemm32<<<dim3(DMODEL / 128, KSPLIT), 128>>>((const float*)p_attn, wo, (float*)p_out_part, DMODEL);
    final_reduce<<<(BATCH * DMODEL) / 256, 256>>>(out);
}